// round 5
// baseline (speedup 1.0000x reference)
#include <cuda_runtime.h>

#define NSEG 128
#define EDIM 128
#define NHEAD 4
#define TILE 128
#define THREADS 256
#define EPAD 136   // padded row stride for e_s (float4-aligned)

__device__ float g_s[NSEG * NHEAD];
__device__ float g_acc[NSEG * NHEAD * EDIM];
__device__ int   g_is64;
__device__ unsigned int g_done;

__global__ void zero_kernel(const int* __restrict__ b32, int N) {
    int i = blockIdx.x * blockDim.x + threadIdx.x;
    if (i < NSEG * NHEAD * EDIM) g_acc[i] = 0.0f;
    if (i < NSEG * NHEAD)        g_s[i]   = 0.0f;
    if (i == 0) {
        g_done = 0;
        // int64 (LE): the int32 view's high words at the tail are zero.
        int a = b32[N - 1];
        int b = (N >= 3) ? b32[N - 3] : 1;
        int c = (N >= 5) ? b32[N - 5] : 1;
        g_is64 = (a == 0 && b == 0 && c == 0) ? 1 : 0;
    }
}

__global__ __launch_bounds__(THREADS) void att_kernel(
    const float4* __restrict__ x,        // [N, 32] float4 view of [N,128]
    const float4* __restrict__ w,        // [4, 32]
    const void*   __restrict__ batch,
    float* __restrict__ out, int N)
{
    __shared__ float4   w_s[NHEAD * 32];     // [4][32] float4
    __shared__ float    e_s[NHEAD * EPAD];   // [4][EPAD]
    __shared__ int      seg_s[TILE];
    __shared__ unsigned bmask[4];
    __shared__ short    runs[TILE + 1];
    __shared__ int      nrun_s;
    __shared__ int      s_last;

    const int t   = threadIdx.x;
    const int beg = blockIdx.x * TILE;
    const int cnt = min(TILE, N - beg);
    const int is64 = g_is64;

    if (t < NHEAD * 32) w_s[t] = w[t];

    // ---- batch slice (one coalesced load) ----
    if (t < TILE) {
        int seg = 0;
        if (t < cnt) {
            if (is64) seg = (int)((const long long*)batch)[beg + t] & (NSEG - 1);
            else      seg = ((const int*)batch)[beg + t] & (NSEG - 1);
        }
        seg_s[t] = seg;
    }
    __syncthreads();

    // ---- boundary ballot + run list (block-uniform) ----
    if (t < TILE) {
        bool flag = (t < cnt) && (t == 0 || seg_s[t] != seg_s[t - 1]);
        unsigned m = __ballot_sync(0xffffffffu, flag);
        if ((t & 31) == 0) bmask[t >> 5] = m;
    }
    __syncthreads();
    if (t == 0) {
        int k = 0;
        for (int wi = 0; wi < 4; ++wi) {
            unsigned m = bmask[wi];
            while (m) { int b = __ffs(m) - 1; runs[k++] = (short)(wi * 32 + b); m &= m - 1; }
        }
        runs[k] = (short)cnt;
        nrun_s = k;
    }

    // ---- S1: per-thread dot (row = t>>1, two heads), exp -> smem ----
    {
        const int row = t >> 1;
        const int h0  = (t & 1) * 2;
        float e0 = 0.0f, e1 = 0.0f;
        if (row < cnt) {
            const float4* xr = x + (size_t)(beg + row) * 32;
            float4 a0 = make_float4(0, 0, 0, 0);
            float4 a1 = make_float4(0, 0, 0, 0);
#pragma unroll 4
            for (int e4 = 0; e4 < 32; ++e4) {
                float4 xv = xr[e4];
                float4 w0 = w_s[h0 * 32 + e4];
                float4 w1 = w_s[h0 * 32 + 32 + e4];
                a0.x += xv.x * w0.x; a0.y += xv.y * w0.y;
                a0.z += xv.z * w0.z; a0.w += xv.w * w0.w;
                a1.x += xv.x * w1.x; a1.y += xv.y * w1.y;
                a1.z += xv.z * w1.z; a1.w += xv.w * w1.w;
            }
            float d0 = (a0.x + a0.y) + (a0.z + a0.w);
            float d1 = (a1.x + a1.y) + (a1.z + a1.w);
            e0 = __expf(d0);
            e1 = __expf(d1);
        }
        e_s[(h0    ) * EPAD + row] = e0;
        e_s[(h0 + 1) * EPAD + row] = e1;
    }
    __syncthreads();

    // ---- S2: accumulate acc4[h][col4] += e * x (x re-read, L2-hot) ----
    {
        const int col4 = t & 31;
        const int h    = (t >> 5) & 3;
        const int half = t >> 7;                 // warp-uniform
        const int lo_h = half * 64, hi_h = lo_h + 64;
        const float*  eh = &e_s[h * EPAD];
        const float4* xb = x + (size_t)beg * 32 + col4;
        const int nrun = nrun_s;

        for (int ri = 0; ri < nrun; ++ri) {
            int lo = runs[ri], hi = runs[ri + 1];
            int r0 = max(lo, lo_h), r1 = min(hi, hi_h);
            if (r0 < r1) {
                const int seg = seg_s[lo];
                float4 acc = make_float4(0, 0, 0, 0);
                float  accS = 0.0f;
                int r = r0;
                for (; r + 3 < r1; r += 4) {
                    float ea = eh[r], eb = eh[r + 1], ec = eh[r + 2], ed = eh[r + 3];
                    float4 xa = xb[(size_t)(r    ) * 32];
                    float4 xbv= xb[(size_t)(r + 1) * 32];
                    float4 xc = xb[(size_t)(r + 2) * 32];
                    float4 xd = xb[(size_t)(r + 3) * 32];
                    acc.x += ea * xa.x;  acc.y += ea * xa.y;
                    acc.z += ea * xa.z;  acc.w += ea * xa.w;
                    acc.x += eb * xbv.x; acc.y += eb * xbv.y;
                    acc.z += eb * xbv.z; acc.w += eb * xbv.w;
                    acc.x += ec * xc.x;  acc.y += ec * xc.y;
                    acc.z += ec * xc.z;  acc.w += ec * xc.w;
                    acc.x += ed * xd.x;  acc.y += ed * xd.y;
                    acc.z += ed * xd.z;  acc.w += ed * xd.w;
                    accS += (ea + eb) + (ec + ed);
                }
                for (; r < r1; ++r) {
                    float ee = eh[r];
                    float4 xa = xb[(size_t)r * 32];
                    acc.x += ee * xa.x; acc.y += ee * xa.y;
                    acc.z += ee * xa.z; acc.w += ee * xa.w;
                    accS += ee;
                }
                float* base = &g_acc[(seg * NHEAD + h) * EDIM + col4 * 4];
                atomicAdd(base + 0, acc.x);
                atomicAdd(base + 1, acc.y);
                atomicAdd(base + 2, acc.z);
                atomicAdd(base + 3, acc.w);
                if (col4 == 0) atomicAdd(&g_s[seg * NHEAD + h], accS);
            }
        }
    }

    // ---- inline finalize: last block reduces ----
    __threadfence();
    __syncthreads();
    if (t == 0) {
        unsigned int prev = atomicAdd(&g_done, 1u);
        s_last = (prev == (unsigned int)(gridDim.x - 1)) ? 1 : 0;
    }
    __syncthreads();
    if (s_last) {
        for (int i = t; i < NSEG * EDIM; i += THREADS) {
            int b = i >> 7;
            int e = i & 127;
            float r = 0.0f;
#pragma unroll
            for (int h = 0; h < NHEAD; ++h) {
                float av = __ldcg(&g_acc[(b * NHEAD + h) * EDIM + e]);
                float sv = __ldcg(&g_s[b * NHEAD + h]);
                r += av / sv;
            }
            out[i] = r * (1.0f / NHEAD);
        }
    }
}

extern "C" void kernel_launch(void* const* d_in, const int* in_sizes, int n_in,
                              void* d_out, int out_size) {
    const float* x     = (const float*)d_in[0];
    const float* w     = (const float*)d_in[1];
    const void*  batch = d_in[2];

    int N = in_sizes[0] / EDIM;
    int nblk = (N + TILE - 1) / TILE;

    zero_kernel<<<(NSEG * NHEAD * EDIM + 255) / 256, 256>>>((const int*)batch, N);
    att_kernel<<<nblk, THREADS>>>((const float4*)x, (const float4*)w, batch,
                                  (float*)d_out, N);
}